// round 1
// baseline (speedup 1.0000x reference)
#include <cuda_runtime.h>
#include <cuda_bf16.h>
#include <cstdint>

// Problem constants
#define B_    32
#define C_    128
#define CIN_  64
#define COUT_ 128
#define H_    128
#define W_    128
#define HW_   (H_ * W_)

// Scratch (no allocation allowed in kernel_launch)
__device__ float g_chsum[B_ * C_];
__device__ int   g_idx[B_ * CIN_];

// ---------------------------------------------------------------------------
// Kernel 1: per-channel spatial sums. One block per (b, c) channel.
// ---------------------------------------------------------------------------
__global__ __launch_bounds__(256) void chsum_kernel(const float* __restrict__ x) {
    const int ch = blockIdx.x;                      // 0 .. B_*C_-1
    const float4* p = reinterpret_cast<const float4*>(x) + (size_t)ch * (HW_ / 4);
    float s = 0.f;
    for (int i = threadIdx.x; i < HW_ / 4; i += 256) {
        float4 v = p[i];
        s += (v.x + v.y) + (v.z + v.w);
    }
    // warp reduce
    #pragma unroll
    for (int o = 16; o; o >>= 1) s += __shfl_down_sync(0xffffffffu, s, o);
    __shared__ float red[8];
    if ((threadIdx.x & 31) == 0) red[threadIdx.x >> 5] = s;
    __syncthreads();
    if (threadIdx.x < 8) {
        s = red[threadIdx.x];
        #pragma unroll
        for (int o = 4; o; o >>= 1) s += __shfl_down_sync(0xffu, s, o);
        if (threadIdx.x == 0) g_chsum[ch] = s;
    }
}

// ---------------------------------------------------------------------------
// Kernel 2: stable ascending argsort -> first CIN_ channels per batch.
// rank_i = #{j : s_j < s_i} + #{j < i : s_j == s_i}  (matches stable argsort)
// ---------------------------------------------------------------------------
__global__ __launch_bounds__(C_) void select_kernel() {
    const int b = blockIdx.x;
    const int c = threadIdx.x;
    __shared__ float s[C_];
    s[c] = g_chsum[b * C_ + c];
    __syncthreads();
    const float mine = s[c];
    int rank = 0;
    #pragma unroll 8
    for (int j = 0; j < C_; j++) {
        float v = s[j];
        rank += (v < mine) || (v == mine && j < c);
    }
    if (rank < CIN_) g_idx[b * CIN_ + rank] = c;
}

// ---------------------------------------------------------------------------
// Kernel 3: gathered 3x3 conv, fp32 direct.
// Block: one batch, 8 output channels, 8 rows x 128 cols.
// Thread (32x8): 4 output pixels x 8 couts = 32 accumulators.
// All weights for this cout-group live in SMEM for the whole block.
// Input tile (10 x 130 with halo) staged per-ci in SMEM, stride 136 so the
// two float4 reads per row per thread are 16B-aligned and conflict-free.
// Grid x = cout-group (fastest) so blocks sharing an input tile co-reside
// on the chip -> input re-reads served from L2.
// ---------------------------------------------------------------------------
#define COUT_G   8
#define TILE_H   8
#define T_STRIDE 136                                // padded SMEM row stride
#define T_ROWS   (TILE_H + 2)
#define T_COLS   (W_ + 2)

__global__ __launch_bounds__(256, 2) void conv_kernel(
    const float* __restrict__ x,
    const float* __restrict__ w,
    const float* __restrict__ bias,
    float* __restrict__ out)
{
    const int cg = blockIdx.x;                      // 0..15 cout group
    const int yt = blockIdx.y;                      // 0..15 row tile
    const int b  = blockIdx.z;                      // 0..31 batch
    const int tx = threadIdx.x;                     // 0..31
    const int ty = threadIdx.y;                     // 0..7
    const int tid = ty * 32 + tx;

    __shared__ float ws[COUT_G * CIN_ * 9];         // 4608 floats
    __shared__ __align__(16) float tile[T_ROWS * T_STRIDE];
    __shared__ int sidx[CIN_];

    // Preload this group's weights (contiguous 4608 floats) and the gather idx
    const float* wg = w + (size_t)cg * COUT_G * CIN_ * 9;
    for (int i = tid; i < COUT_G * CIN_ * 9; i += 256) ws[i] = wg[i];
    if (tid < CIN_) sidx[tid] = g_idx[b * CIN_ + tid];
    __syncthreads();

    const int y0 = yt * TILE_H;

    float acc[COUT_G][4];
    #pragma unroll
    for (int co = 0; co < COUT_G; co++) {
        float bv = bias[cg * COUT_G + co];
        acc[co][0] = bv; acc[co][1] = bv; acc[co][2] = bv; acc[co][3] = bv;
    }

    for (int ci = 0; ci < CIN_; ci++) {
        const float* xin = x + ((size_t)(b * C_ + sidx[ci])) * HW_;

        // Stage input tile (zero-padded halo). 1300 elems / 256 threads.
        for (int i = tid; i < T_ROWS * T_COLS; i += 256) {
            int r = i / T_COLS;
            int c = i - r * T_COLS;
            int gy = y0 - 1 + r;
            int gx = c - 1;
            float v = 0.f;
            if ((unsigned)gy < (unsigned)H_ && (unsigned)gx < (unsigned)W_)
                v = xin[gy * W_ + gx];
            tile[r * T_STRIDE + c] = v;
        }
        __syncthreads();

        // Per-thread input window: 3 rows x 6 cols as 2x float4 per row
        float in[3][6];
        #pragma unroll
        for (int dy = 0; dy < 3; dy++) {
            const float* rp = &tile[(ty + dy) * T_STRIDE + 4 * tx];
            float4 a = *reinterpret_cast<const float4*>(rp);
            float4 c4 = *reinterpret_cast<const float4*>(rp + 4);
            in[dy][0] = a.x; in[dy][1] = a.y; in[dy][2] = a.z; in[dy][3] = a.w;
            in[dy][4] = c4.x; in[dy][5] = c4.y;
        }

        #pragma unroll
        for (int co = 0; co < COUT_G; co++) {
            const float* wp = ws + ((size_t)co * CIN_ + ci) * 9;
            #pragma unroll
            for (int ky = 0; ky < 3; ky++) {
                #pragma unroll
                for (int kx = 0; kx < 3; kx++) {
                    float wv = wp[ky * 3 + kx];
                    #pragma unroll
                    for (int p = 0; p < 4; p++)
                        acc[co][p] += in[ky][p + kx] * wv;
                }
            }
        }
        __syncthreads();  // tile reused next iteration
    }

    // Write 8 couts x 4 pixels as float4 stores
    const int gy = y0 + ty;
    #pragma unroll
    for (int co = 0; co < COUT_G; co++) {
        size_t off = (((size_t)b * COUT_ + cg * COUT_G + co) * H_ + gy) * W_ + 4 * tx;
        float4 v = make_float4(acc[co][0], acc[co][1], acc[co][2], acc[co][3]);
        *reinterpret_cast<float4*>(out + off) = v;
    }
}

// ---------------------------------------------------------------------------
extern "C" void kernel_launch(void* const* d_in, const int* in_sizes, int n_in,
                              void* d_out, int out_size) {
    const float* x  = (const float*)d_in[0];   // [32,128,128,128]
    const float* w  = (const float*)d_in[1];   // [128,64,3,3]
    const float* bv = (const float*)d_in[2];   // [128]
    float* out = (float*)d_out;

    chsum_kernel<<<B_ * C_, 256>>>(x);
    select_kernel<<<B_, C_>>>();

    dim3 grid(COUT_ / COUT_G, H_ / TILE_H, B_);  // (16, 16, 32), cout fastest
    dim3 block(32, TILE_H);
    conv_kernel<<<grid, block>>>(x, w, bv, out);
}

// round 3
// speedup vs baseline: 3.7432x; 3.7432x over previous
#include <cuda_runtime.h>
#include <cuda_bf16.h>
#include <cstdint>

// ---------------------------------------------------------------------------
// Problem constants
// ---------------------------------------------------------------------------
#define B_    32
#define C_    128
#define CIN_  64
#define COUT_ 128
#define H_    128
#define W_    128
#define HW_   (H_ * W_)
#define NCHUNK 27            // 18 seg1 (hi,lo)x(hw,hw) + 9 seg2 hi x lw
#define SEG1   18

// ---------------------------------------------------------------------------
// Device scratch (static allocations only)
// ---------------------------------------------------------------------------
__device__ float    g_chsum[B_ * C_];
__device__ int      g_idx[B_ * CIN_];
// Xil[b][y][x][ci] : u32 word = hi(bf16) | lo(bf16)<<16   (134 MB)
__device__ __align__(128) uint32_t g_Xil[(size_t)B_ * H_ * W_ * CIN_];
// Xhi[b][y][x][ciPair] : u32 = hi(2j) | hi(2j+1)<<16       (67 MB)
__device__ __align__(128) uint32_t g_Xhi[(size_t)B_ * H_ * W_ * (CIN_ / 2)];
// Wsplit: 27 chunks x [128 couts x 64 bf16] (linear, k contiguous)
__device__ __align__(128) unsigned short g_Wsplit[NCHUNK * COUT_ * 64];

// ---------------------------------------------------------------------------
// Helpers
// ---------------------------------------------------------------------------
__device__ __forceinline__ uint32_t smem_u32(const void* p) {
    uint32_t a;
    asm("{ .reg .u64 t; cvta.to.shared.u64 t, %1; cvt.u32.u64 %0, t; }" : "=r"(a) : "l"(p));
    return a;
}
__device__ __forceinline__ unsigned short bf16_bits(float v) {
    __nv_bfloat16 h = __float2bfloat16_rn(v);
    return *reinterpret_cast<unsigned short*>(&h);
}
__device__ __forceinline__ float bf16_val(unsigned short u) {
    __nv_bfloat16 h = *reinterpret_cast<__nv_bfloat16*>(&u);
    return __bfloat162float(h);
}

// Swizzled LDS.32: tile rows are 128B (32 words); word = row*32 + (cw ^ ((row&7)<<2))
__device__ __forceinline__ uint32_t ldsw(uint32_t base, int row, int cw) {
    uint32_t addr = base + (uint32_t)row * 128u + (uint32_t)(((cw << 2) ^ ((row & 7) << 4)));
    uint32_t v;
    asm volatile("ld.shared.b32 %0, [%1];" : "=r"(v) : "r"(addr));
    return v;
}

__device__ __forceinline__ void mma16816(float* d, uint32_t a0, uint32_t a1,
                                         uint32_t a2, uint32_t a3,
                                         uint32_t b0, uint32_t b1) {
    asm volatile(
        "mma.sync.aligned.m16n8k16.row.col.f32.bf16.bf16.f32 "
        "{%0,%1,%2,%3}, {%4,%5,%6,%7}, {%8,%9}, {%0,%1,%2,%3};"
        : "+f"(d[0]), "+f"(d[1]), "+f"(d[2]), "+f"(d[3])
        : "r"(a0), "r"(a1), "r"(a2), "r"(a3), "r"(b0), "r"(b1));
}

// ---------------------------------------------------------------------------
// Kernel 1: per-channel sums
// ---------------------------------------------------------------------------
__global__ __launch_bounds__(256) void chsum_kernel(const float* __restrict__ x) {
    const int ch = blockIdx.x;
    const float4* p = reinterpret_cast<const float4*>(x) + (size_t)ch * (HW_ / 4);
    float s = 0.f;
    for (int i = threadIdx.x; i < HW_ / 4; i += 256) {
        float4 v = p[i];
        s += (v.x + v.y) + (v.z + v.w);
    }
    #pragma unroll
    for (int o = 16; o; o >>= 1) s += __shfl_down_sync(0xffffffffu, s, o);
    __shared__ float red[8];
    if ((threadIdx.x & 31) == 0) red[threadIdx.x >> 5] = s;
    __syncthreads();
    if (threadIdx.x < 8) {
        s = red[threadIdx.x];
        #pragma unroll
        for (int o = 4; o; o >>= 1) s += __shfl_down_sync(0xffu, s, o);
        if (threadIdx.x == 0) g_chsum[ch] = s;
    }
}

// ---------------------------------------------------------------------------
// Kernel 2: stable ascending rank select (first CIN_)
// ---------------------------------------------------------------------------
__global__ __launch_bounds__(C_) void select_kernel() {
    const int b = blockIdx.x, c = threadIdx.x;
    __shared__ float s[C_];
    s[c] = g_chsum[b * C_ + c];
    __syncthreads();
    const float mine = s[c];
    int rank = 0;
    #pragma unroll 8
    for (int j = 0; j < C_; j++) {
        float v = s[j];
        rank += (v < mine) || (v == mine && j < c);
    }
    if (rank < CIN_) g_idx[b * CIN_ + rank] = c;
}

// ---------------------------------------------------------------------------
// Kernel 3: gather selected channels, CHW->HWC transpose, hi/lo bf16 split
// ---------------------------------------------------------------------------
__global__ __launch_bounds__(256) void gather_split_kernel(const float* __restrict__ x) {
    const int y = blockIdx.x, b = blockIdx.y;
    const int tid = threadIdx.x;
    __shared__ float sv[CIN_][W_ + 1];

    for (int i = tid; i < CIN_ * W_; i += 256) {
        int ci = i >> 7, xx = i & 127;
        int src_c = g_idx[b * CIN_ + ci];
        sv[ci][xx] = x[(((size_t)b * C_ + src_c) * H_ + y) * W_ + xx];
    }
    __syncthreads();

    uint32_t* dst_il = g_Xil + ((size_t)(b * H_ + y)) * W_ * CIN_;
    for (int o = tid; o < W_ * CIN_; o += 256) {
        int xx = o >> 6, ci = o & 63;
        float v = sv[ci][xx];
        unsigned short hu = bf16_bits(v);
        unsigned short lu = bf16_bits(v - bf16_val(hu));
        dst_il[o] = (uint32_t)hu | ((uint32_t)lu << 16);
    }
    uint32_t* dst_hi = g_Xhi + ((size_t)(b * H_ + y)) * W_ * (CIN_ / 2);
    for (int o = tid; o < W_ * (CIN_ / 2); o += 256) {
        int xx = o >> 5, cw = o & 31;
        unsigned short h0 = bf16_bits(sv[2 * cw][xx]);
        unsigned short h1 = bf16_bits(sv[2 * cw + 1][xx]);
        dst_hi[o] = (uint32_t)h0 | ((uint32_t)h1 << 16);
    }
}

// ---------------------------------------------------------------------------
// Kernel 4: weight split/reorder (linear layout: [chunk][cout][k])
//   chunk c<18: tap=c/2, half=c%2; col k -> hw(ci=half*32+k/2) (pair-duplicated)
//   chunk c>=18: tap=c-18; col k -> lw(ci=k)
// ---------------------------------------------------------------------------
__global__ __launch_bounds__(256) void wprep_kernel(const float* __restrict__ w) {
    int t = blockIdx.x * 256 + threadIdx.x;
    if (t >= NCHUNK * COUT_ * 64) return;
    int c = t >> 13;
    int r = (t >> 6) & 127;
    int k = t & 63;
    unsigned short val;
    if (c < SEG1) {
        int tap = c >> 1, ci = (c & 1) * 32 + (k >> 1);
        val = bf16_bits(w[r * (CIN_ * 9) + ci * 9 + tap]);
    } else {
        int tap = c - SEG1, ci = k;
        float wf = w[r * (CIN_ * 9) + ci * 9 + tap];
        unsigned short hu = bf16_bits(wf);
        val = bf16_bits(wf - bf16_val(hu));
    }
    g_Wsplit[t] = val;
}

// ---------------------------------------------------------------------------
// Kernel 5: conv as implicit GEMM with mma.sync bf16.
//   CTA = (batch b, 2 output rows). M=256 pixels, N=128 couts, K=27x64.
//   16 warps, warp tile m32 x n64. Double-buffered cp.async staging.
// SMEM (dynamic 96KB): A0[32K] A1[32K] B0[16K] B1[16K]; epilogue reuses base.
// ---------------------------------------------------------------------------
#define EPI_STRIDE 292            // words; 292 % 32 == 4 -> conflict-free STS

extern __shared__ char dynsmem[];

__global__ __launch_bounds__(512, 1) void conv_mma_kernel(
    const float* __restrict__ bias, float* __restrict__ out)
{
    const int ytile = blockIdx.x;             // 0..63  (2 rows each)
    const int b = blockIdx.y;                 // 0..31
    const int tid = threadIdx.x;
    const int wid = tid >> 5;
    const int lane = tid & 31;
    const int g = lane >> 2;                  // group id 0..7
    const int t4 = lane & 3;                  // thread-in-group 0..3
    const int wm = wid & 7;                   // m tile 0..7 (rows of 32)
    const int wn = wid >> 3;                  // n tile 0..1 (cols of 64)
    const int y0 = ytile * 2;

    char* Abuf[2] = { dynsmem, dynsmem + 32768 };
    char* Bbuf[2] = { dynsmem + 65536, dynsmem + 81920 };
    float* epi = reinterpret_cast<float*>(dynsmem);

    __shared__ float sbias[COUT_];
    if (tid < COUT_) sbias[tid] = bias[tid];

    float acc[2][8][4];
    #pragma unroll
    for (int mt = 0; mt < 2; mt++)
        #pragma unroll
        for (int nt = 0; nt < 8; nt++)
            #pragma unroll
            for (int r = 0; r < 4; r++) acc[mt][nt][r] = 0.f;

    // ---- chunk prefetch: A (256 rows x 128B) + B (128 rows x 128B) ----
    auto prefetch = [&](int c, int buf) {
        int tap = (c < SEG1) ? (c >> 1) : (c - SEG1);
        int ky = tap / 3, kx = tap - ky * 3;
        // A: 2048 16B chunks, 4 per thread
        #pragma unroll
        for (int it = 0; it < 4; it++) {
            int i = tid + it * 512;
            int r = i >> 3, j = i & 7;        // row 0..255, 16B chunk 0..7
            int yl = r >> 7, x = r & 127;
            int yy = y0 + yl + ky - 1;
            int xx = x + kx - 1;
            bool valid = ((unsigned)yy < (unsigned)H_) && ((unsigned)xx < (unsigned)W_);
            int yc = valid ? yy : 0;
            int xc = valid ? xx : 0;
            const char* src;
            if (c < SEG1)
                src = reinterpret_cast<const char*>(
                    g_Xil + (((size_t)(b * H_ + yc) * W_ + xc) * CIN_ + (c & 1) * 32));
            else
                src = reinterpret_cast<const char*>(
                    g_Xhi + ((size_t)(b * H_ + yc) * W_ + xc) * (CIN_ / 2));
            uint32_t dst = smem_u32(Abuf[buf]) + (uint32_t)r * 128u +
                           (uint32_t)((j * 16) ^ ((r & 7) << 4));
            uint32_t sz = valid ? 16u : 0u;
            asm volatile("cp.async.cg.shared.global [%0], [%1], 16, %2;"
                         :: "r"(dst), "l"(src + j * 16), "r"(sz));
        }
        // B: 1024 16B chunks, 2 per thread
        const char* wsrc = reinterpret_cast<const char*>(g_Wsplit) + (size_t)c * 16384;
        #pragma unroll
        for (int it = 0; it < 2; it++) {
            int i = tid + it * 512;
            int r = i >> 3, j = i & 7;        // cout row, chunk
            uint32_t dst = smem_u32(Bbuf[buf]) + (uint32_t)r * 128u +
                           (uint32_t)((j * 16) ^ ((r & 7) << 4));
            asm volatile("cp.async.cg.shared.global [%0], [%1], 16, 16;"
                         :: "r"(dst), "l"(wsrc + (size_t)r * 128 + j * 16));
        }
        asm volatile("cp.async.commit_group;" ::: "memory");
    };

    prefetch(0, 0);

    for (int c = 0; c < NCHUNK; c++) {
        const int buf = c & 1;
        if (c < NCHUNK - 1) {
            prefetch(c + 1, buf ^ 1);
            asm volatile("cp.async.wait_group 1;" ::: "memory");
        } else {
            asm volatile("cp.async.wait_group 0;" ::: "memory");
        }
        __syncthreads();

        const uint32_t Ab = smem_u32(Abuf[buf]);
        const uint32_t Bb = smem_u32(Bbuf[buf]);

        #pragma unroll
        for (int ks = 0; ks < 4; ks++) {
            const int c0 = ks * 8;
            uint32_t bf[8][2];
            #pragma unroll
            for (int nt = 0; nt < 8; nt++) {
                int row = wn * 64 + nt * 8 + g;
                bf[nt][0] = ldsw(Bb, row, c0 + t4);
                bf[nt][1] = ldsw(Bb, row, c0 + 4 + t4);
            }
            #pragma unroll
            for (int mt = 0; mt < 2; mt++) {
                int rowa = wm * 32 + mt * 16 + g;
                uint32_t a0 = ldsw(Ab, rowa,     c0 + t4);
                uint32_t a1 = ldsw(Ab, rowa + 8, c0 + t4);
                uint32_t a2 = ldsw(Ab, rowa,     c0 + 4 + t4);
                uint32_t a3 = ldsw(Ab, rowa + 8, c0 + 4 + t4);
                #pragma unroll
                for (int nt = 0; nt < 8; nt++)
                    mma16816(acc[mt][nt], a0, a1, a2, a3, bf[nt][0], bf[nt][1]);
            }
        }
        __syncthreads();
    }

    // ---- epilogue: 2 passes of 64 couts through SMEM, coalesced NCHW stores ----
    #pragma unroll
    for (int p = 0; p < 2; p++) {
        if (wn == p) {
            #pragma unroll
            for (int mt = 0; mt < 2; mt++) {
                int rowm = wm * 32 + mt * 16 + g;
                #pragma unroll
                for (int nt = 0; nt < 8; nt++) {
                    int nl = nt * 8 + 2 * t4;
                    epi[(size_t)nl * EPI_STRIDE + rowm]           = acc[mt][nt][0];
                    epi[(size_t)(nl + 1) * EPI_STRIDE + rowm]     = acc[mt][nt][1];
                    epi[(size_t)nl * EPI_STRIDE + rowm + 8]       = acc[mt][nt][2];
                    epi[(size_t)(nl + 1) * EPI_STRIDE + rowm + 8] = acc[mt][nt][3];
                }
            }
        }
        __syncthreads();
        #pragma unroll
        for (int it = 0; it < 8; it++) {
            int i = tid + it * 512;           // 0..4095 float4s
            int nl = i >> 6, mv = i & 63;
            int m = mv * 4;
            float4 v = *reinterpret_cast<float4*>(&epi[(size_t)nl * EPI_STRIDE + m]);
            float bv = sbias[p * 64 + nl];
            v.x += bv; v.y += bv; v.z += bv; v.w += bv;
            int yy = y0 + (m >> 7);
            int xx = m & 127;
            *reinterpret_cast<float4*>(
                out + (((size_t)b * COUT_ + p * 64 + nl) * H_ + yy) * W_ + xx) = v;
        }
        __syncthreads();
    }
}

// ---------------------------------------------------------------------------
extern "C" void kernel_launch(void* const* d_in, const int* in_sizes, int n_in,
                              void* d_out, int out_size) {
    const float* x  = (const float*)d_in[0];   // [32,128,128,128]
    const float* w  = (const float*)d_in[1];   // [128,64,3,3]
    const float* bv = (const float*)d_in[2];   // [128]
    float* out = (float*)d_out;

    static bool attr_set = false;
    if (!attr_set) {
        cudaFuncSetAttribute(conv_mma_kernel,
                             cudaFuncAttributeMaxDynamicSharedMemorySize, 98304);
        attr_set = true;
    }

    chsum_kernel<<<B_ * C_, 256>>>(x);
    select_kernel<<<B_, C_>>>();
    gather_split_kernel<<<dim3(H_, B_), 256>>>(x);
    wprep_kernel<<<(NCHUNK * COUT_ * 64 + 255) / 256, 256>>>(w);
    conv_mma_kernel<<<dim3(H_ / 2, B_), 512, 98304>>>(bv, out);
}

// round 4
// speedup vs baseline: 4.1117x; 1.0984x over previous
#include <cuda_runtime.h>
#include <cuda_bf16.h>
#include <cstdint>

// ---------------------------------------------------------------------------
// Problem constants
// ---------------------------------------------------------------------------
#define B_    32
#define C_    128
#define CIN_  64
#define COUT_ 128
#define H_    128
#define W_    128
#define HW_   (H_ * W_)
#define NCHUNK 27            // 18 seg1 (hi,lo)x(hw,hw) + 9 seg2 hi x lw
#define SEG1   18

// ---------------------------------------------------------------------------
// Device scratch (static allocations only)
// ---------------------------------------------------------------------------
__device__ float    g_chsum[B_ * C_];
__device__ int      g_idx[B_ * CIN_];
// Xil[b][y][x][ci] : u32 word = hi(bf16) | lo(bf16)<<16   (134 MB)
__device__ __align__(128) uint32_t g_Xil[(size_t)B_ * H_ * W_ * CIN_];
// Xhi[b][y][x][ciPair] : u32 = hi(2j) | hi(2j+1)<<16       (67 MB)
__device__ __align__(128) uint32_t g_Xhi[(size_t)B_ * H_ * W_ * (CIN_ / 2)];
// Wsplit: 27 chunks x [128 couts x 64 bf16] (linear, k contiguous)
__device__ __align__(128) unsigned short g_Wsplit[NCHUNK * COUT_ * 64];

// ---------------------------------------------------------------------------
// Helpers
// ---------------------------------------------------------------------------
__device__ __forceinline__ uint32_t smem_u32(const void* p) {
    uint32_t a;
    asm("{ .reg .u64 t; cvta.to.shared.u64 t, %1; cvt.u32.u64 %0, t; }" : "=r"(a) : "l"(p));
    return a;
}
__device__ __forceinline__ unsigned short bf16_bits(float v) {
    __nv_bfloat16 h = __float2bfloat16_rn(v);
    return *reinterpret_cast<unsigned short*>(&h);
}
__device__ __forceinline__ float bf16_val(unsigned short u) {
    __nv_bfloat16 h = *reinterpret_cast<__nv_bfloat16*>(&u);
    return __bfloat162float(h);
}

// Swizzled LDS.32 with runtime row stride; 128B swizzle atom within a row block
__device__ __forceinline__ uint32_t ldsw(uint32_t base, int row, int cw, int stride) {
    uint32_t addr = base + (uint32_t)(row * stride) +
                    (uint32_t)(((cw << 2) ^ ((row & 7) << 4)));
    uint32_t v;
    asm volatile("ld.shared.b32 %0, [%1];" : "=r"(v) : "r"(addr));
    return v;
}

__device__ __forceinline__ void mma16816(float* d, uint32_t a0, uint32_t a1,
                                         uint32_t a2, uint32_t a3,
                                         uint32_t b0, uint32_t b1) {
    asm volatile(
        "mma.sync.aligned.m16n8k16.row.col.f32.bf16.bf16.f32 "
        "{%0,%1,%2,%3}, {%4,%5,%6,%7}, {%8,%9}, {%0,%1,%2,%3};"
        : "+f"(d[0]), "+f"(d[1]), "+f"(d[2]), "+f"(d[3])
        : "r"(a0), "r"(a1), "r"(a2), "r"(a3), "r"(b0), "r"(b1));
}

// ---------------------------------------------------------------------------
// Kernel 1: per-channel sums
// ---------------------------------------------------------------------------
__global__ __launch_bounds__(256) void chsum_kernel(const float* __restrict__ x) {
    const int ch = blockIdx.x;
    const float4* p = reinterpret_cast<const float4*>(x) + (size_t)ch * (HW_ / 4);
    float s = 0.f;
    for (int i = threadIdx.x; i < HW_ / 4; i += 256) {
        float4 v = p[i];
        s += (v.x + v.y) + (v.z + v.w);
    }
    #pragma unroll
    for (int o = 16; o; o >>= 1) s += __shfl_down_sync(0xffffffffu, s, o);
    __shared__ float red[8];
    if ((threadIdx.x & 31) == 0) red[threadIdx.x >> 5] = s;
    __syncthreads();
    if (threadIdx.x < 8) {
        s = red[threadIdx.x];
        #pragma unroll
        for (int o = 4; o; o >>= 1) s += __shfl_down_sync(0xffu, s, o);
        if (threadIdx.x == 0) g_chsum[ch] = s;
    }
}

// ---------------------------------------------------------------------------
// Kernel 2: select (blocks 0..31) + weight split/reorder (blocks 32..895)
// ---------------------------------------------------------------------------
__global__ __launch_bounds__(256) void select_wprep_kernel(const float* __restrict__ w) {
    if (blockIdx.x < B_) {
        if (threadIdx.x >= C_) return;
        const int b = blockIdx.x, c = threadIdx.x;
        __shared__ float s[C_];
        s[c] = g_chsum[b * C_ + c];
        __syncthreads();
        const float mine = s[c];
        int rank = 0;
        #pragma unroll 8
        for (int j = 0; j < C_; j++) {
            float v = s[j];
            rank += (v < mine) || (v == mine && j < c);
        }
        if (rank < CIN_) g_idx[b * CIN_ + rank] = c;
    } else {
        int t = (blockIdx.x - B_) * 256 + threadIdx.x;
        if (t >= NCHUNK * COUT_ * 64) return;
        int c = t >> 13;
        int r = (t >> 6) & 127;
        int k = t & 63;
        unsigned short val;
        if (c < SEG1) {
            int tap = c >> 1, ci = (c & 1) * 32 + (k >> 1);
            val = bf16_bits(w[r * (CIN_ * 9) + ci * 9 + tap]);
        } else {
            int tap = c - SEG1, ci = k;
            float wf = w[r * (CIN_ * 9) + ci * 9 + tap];
            unsigned short hu = bf16_bits(wf);
            val = bf16_bits(wf - bf16_val(hu));
        }
        g_Wsplit[t] = val;
    }
}

// ---------------------------------------------------------------------------
// Kernel 3: gather selected channels, CHW->HWC transpose, hi/lo bf16 split
// ---------------------------------------------------------------------------
__global__ __launch_bounds__(256) void gather_split_kernel(const float* __restrict__ x) {
    const int y = blockIdx.x, b = blockIdx.y;
    const int tid = threadIdx.x;
    __shared__ float sv[CIN_][W_ + 1];

    for (int i = tid; i < CIN_ * W_; i += 256) {
        int ci = i >> 7, xx = i & 127;
        int src_c = g_idx[b * CIN_ + ci];
        sv[ci][xx] = x[(((size_t)b * C_ + src_c) * H_ + y) * W_ + xx];
    }
    __syncthreads();

    uint32_t* dst_il = g_Xil + ((size_t)(b * H_ + y)) * W_ * CIN_;
    for (int o = tid; o < W_ * CIN_; o += 256) {
        int xx = o >> 6, ci = o & 63;
        float v = sv[ci][xx];
        unsigned short hu = bf16_bits(v);
        unsigned short lu = bf16_bits(v - bf16_val(hu));
        dst_il[o] = (uint32_t)hu | ((uint32_t)lu << 16);
    }
    uint32_t* dst_hi = g_Xhi + ((size_t)(b * H_ + y)) * W_ * (CIN_ / 2);
    for (int o = tid; o < W_ * (CIN_ / 2); o += 256) {
        int xx = o >> 5, cw = o & 31;
        unsigned short h0 = bf16_bits(sv[2 * cw][xx]);
        unsigned short h1 = bf16_bits(sv[2 * cw + 1][xx]);
        dst_hi[o] = (uint32_t)h0 | ((uint32_t)h1 << 16);
    }
}

// ---------------------------------------------------------------------------
// Kernel 4: conv implicit GEMM, mma.sync bf16, warp tile m64 x n64.
//   CTA = (batch b, 2 output rows). M=256 pixels, N=128 couts. 8 warps.
//   A staged per (seg, ky) stage with 1-pixel halo: 260 rows; chunks within a
//   stage read the tile at row offset +kx. K total = 27 x 64.
// SMEM (165888B): A0[66560] A1[66560] B0[16384] B1[16384]; epilogue reuses A0.
// ---------------------------------------------------------------------------
#define EPI_STRIDE 260            // words; 260 % 32 == 4 -> conflict-free STS
#define A_STAGE_BYTES 66560       // 260 rows x 256B
#define SMEM_TOTAL (2 * A_STAGE_BYTES + 2 * 16384)

extern __shared__ char dynsmem[];

__device__ __forceinline__ int chunk_stage(int t) {
    return (t < SEG1) ? (t / 6) : (3 + (t - SEG1) / 3);
}

__global__ __launch_bounds__(256, 1) void conv_mma_kernel(
    const float* __restrict__ bias, float* __restrict__ out)
{
    const int ytile = blockIdx.x;             // 0..63  (2 rows each)
    const int b = blockIdx.y;                 // 0..31
    const int tid = threadIdx.x;
    const int wid = tid >> 5;
    const int lane = tid & 31;
    const int g = lane >> 2;                  // 0..7
    const int t4 = lane & 3;                  // 0..3
    const int wm = wid & 3;                   // m tile 0..3 (rows of 64)
    const int wn = wid >> 2;                  // n tile 0..1 (cols of 64)
    const int y0 = ytile * 2;

    char* Abuf[2] = { dynsmem, dynsmem + A_STAGE_BYTES };
    char* Bbuf[2] = { dynsmem + 2 * A_STAGE_BYTES, dynsmem + 2 * A_STAGE_BYTES + 16384 };
    float* epi = reinterpret_cast<float*>(dynsmem);

    __shared__ float sbias[COUT_];
    if (tid < COUT_) sbias[tid] = bias[tid];

    float acc[4][8][4];
    #pragma unroll
    for (int mt = 0; mt < 4; mt++)
        #pragma unroll
        for (int nt = 0; nt < 8; nt++)
            #pragma unroll
            for (int r = 0; r < 4; r++) acc[mt][nt][r] = 0.f;

    // ---- A stage prefetch: tile rows r = yl*130 + xp; input (y0+yl+ky-1, xp-1)
    auto prefetchA = [&](int s, int buf) {
        const uint32_t abase = smem_u32(Abuf[buf]);
        if (s < 3) {
            const int ky = s;
            #pragma unroll
            for (int it = 0; it < 17; it++) {
                int i = tid + it * 256;
                if (i < 260 * 16) {
                    int r = i >> 4, j = i & 15;
                    int yl = (r >= 130) ? 1 : 0;
                    int xp = r - yl * 130;
                    int yy = y0 + yl + ky - 1;
                    int xx = xp - 1;
                    bool valid = ((unsigned)yy < (unsigned)H_) && ((unsigned)xx < (unsigned)W_);
                    int yc = valid ? yy : 0, xc = valid ? xx : 0;
                    const char* src = reinterpret_cast<const char*>(
                        g_Xil + (((size_t)(b * H_ + yc) * W_ + xc) * CIN_)) + j * 16;
                    uint32_t dst = abase + (uint32_t)r * 256u + (uint32_t)((j >> 3) * 128) +
                                   (uint32_t)(((j & 7) * 16) ^ ((r & 7) << 4));
                    uint32_t sz = valid ? 16u : 0u;
                    asm volatile("cp.async.cg.shared.global [%0], [%1], 16, %2;"
                                 :: "r"(dst), "l"(src), "r"(sz));
                }
            }
        } else {
            const int ky = s - 3;
            #pragma unroll
            for (int it = 0; it < 9; it++) {
                int i = tid + it * 256;
                if (i < 260 * 8) {
                    int r = i >> 3, j = i & 7;
                    int yl = (r >= 130) ? 1 : 0;
                    int xp = r - yl * 130;
                    int yy = y0 + yl + ky - 1;
                    int xx = xp - 1;
                    bool valid = ((unsigned)yy < (unsigned)H_) && ((unsigned)xx < (unsigned)W_);
                    int yc = valid ? yy : 0, xc = valid ? xx : 0;
                    const char* src = reinterpret_cast<const char*>(
                        g_Xhi + (((size_t)(b * H_ + yc) * W_ + xc) * (CIN_ / 2))) + j * 16;
                    uint32_t dst = abase + (uint32_t)r * 128u +
                                   (uint32_t)((j * 16) ^ ((r & 7) << 4));
                    uint32_t sz = valid ? 16u : 0u;
                    asm volatile("cp.async.cg.shared.global [%0], [%1], 16, %2;"
                                 :: "r"(dst), "l"(src), "r"(sz));
                }
            }
        }
    };

    // ---- B chunk prefetch: 16KB
    auto prefetchB = [&](int t, int buf) {
        int c;
        if (t < SEG1) {
            int ky = t / 6, j = t % 6, kx = j % 3, half = j / 3;
            c = (ky * 3 + kx) * 2 + half;
        } else c = t;
        const char* wsrc = reinterpret_cast<const char*>(g_Wsplit) + (size_t)c * 16384;
        const uint32_t bbase = smem_u32(Bbuf[buf]);
        #pragma unroll
        for (int it = 0; it < 4; it++) {
            int i = tid + it * 256;
            int r = i >> 3, j = i & 7;
            uint32_t dst = bbase + (uint32_t)r * 128u +
                           (uint32_t)((j * 16) ^ ((r & 7) << 4));
            asm volatile("cp.async.cg.shared.global [%0], [%1], 16, 16;"
                         :: "r"(dst), "l"(wsrc + (size_t)r * 128 + j * 16));
        }
    };

    // Pre-loop: stage-0 A + chunk-0 B as one group
    prefetchA(0, 0);
    prefetchB(0, 0);
    asm volatile("cp.async.commit_group;" ::: "memory");

    for (int t = 0; t < NCHUNK; t++) {
        const int s = chunk_stage(t);
        const int nxt = t + 1;
        if (nxt < NCHUNK) {
            prefetchB(nxt, nxt & 1);
            int sn = chunk_stage(nxt);
            if (sn != s) prefetchA(sn, sn & 1);
            asm volatile("cp.async.commit_group;" ::: "memory");
            asm volatile("cp.async.wait_group 1;" ::: "memory");
        } else {
            asm volatile("cp.async.wait_group 0;" ::: "memory");
        }
        __syncthreads();

        // chunk params
        int stride, halfoff, kx;
        if (t < SEG1) {
            int j = t % 6;
            kx = j % 3; halfoff = (j / 3) * 128; stride = 256;
        } else {
            kx = (t - SEG1) % 3; halfoff = 0; stride = 128;
        }
        const uint32_t Ab = smem_u32(Abuf[s & 1]) + halfoff;
        const uint32_t Bb = smem_u32(Bbuf[t & 1]);
        const int rowadd = ((wm >= 2) ? 2 : 0) + kx;   // uniform per warp

        #pragma unroll
        for (int ks = 0; ks < 4; ks++) {
            const int c0 = ks * 8;
            uint32_t bf[8][2];
            #pragma unroll
            for (int nt = 0; nt < 8; nt++) {
                int row = wn * 64 + nt * 8 + g;
                bf[nt][0] = ldsw(Bb, row, c0 + t4, 128);
                bf[nt][1] = ldsw(Bb, row, c0 + 4 + t4, 128);
            }
            #pragma unroll
            for (int mt = 0; mt < 4; mt++) {
                int ra = wm * 64 + mt * 16 + g + rowadd;
                uint32_t a0 = ldsw(Ab, ra,     c0 + t4, stride);
                uint32_t a1 = ldsw(Ab, ra + 8, c0 + t4, stride);
                uint32_t a2 = ldsw(Ab, ra,     c0 + 4 + t4, stride);
                uint32_t a3 = ldsw(Ab, ra + 8, c0 + 4 + t4, stride);
                #pragma unroll
                for (int nt = 0; nt < 8; nt++)
                    mma16816(acc[mt][nt], a0, a1, a2, a3, bf[nt][0], bf[nt][1]);
            }
        }
        __syncthreads();   // protect buffers from next iteration's prefetch
    }

    // ---- epilogue: 2 passes of 64 couts through SMEM, coalesced NCHW stores ----
    #pragma unroll
    for (int p = 0; p < 2; p++) {
        if (wn == p) {
            #pragma unroll
            for (int mt = 0; mt < 4; mt++) {
                int rowm = wm * 64 + mt * 16 + g;
                #pragma unroll
                for (int nt = 0; nt < 8; nt++) {
                    int nl = nt * 8 + 2 * t4;
                    epi[(size_t)nl * EPI_STRIDE + rowm]           = acc[mt][nt][0];
                    epi[(size_t)(nl + 1) * EPI_STRIDE + rowm]     = acc[mt][nt][1];
                    epi[(size_t)nl * EPI_STRIDE + rowm + 8]       = acc[mt][nt][2];
                    epi[(size_t)(nl + 1) * EPI_STRIDE + rowm + 8] = acc[mt][nt][3];
                }
            }
        }
        __syncthreads();
        #pragma unroll
        for (int it = 0; it < 16; it++) {
            int i = tid + it * 256;           // 0..4095 float4s
            int nl = i >> 6, mv = i & 63;
            int m = mv * 4;
            float4 v = *reinterpret_cast<float4*>(&epi[(size_t)nl * EPI_STRIDE + m]);
            float bv = sbias[p * 64 + nl];
            v.x += bv; v.y += bv; v.z += bv; v.w += bv;
            int yy = y0 + (m >> 7);
            int xx = m & 127;
            *reinterpret_cast<float4*>(
                out + (((size_t)b * COUT_ + p * 64 + nl) * H_ + yy) * W_ + xx) = v;
        }
        __syncthreads();
    }
}

// ---------------------------------------------------------------------------
extern "C" void kernel_launch(void* const* d_in, const int* in_sizes, int n_in,
                              void* d_out, int out_size) {
    const float* x  = (const float*)d_in[0];   // [32,128,128,128]
    const float* w  = (const float*)d_in[1];   // [128,64,3,3]
    const float* bv = (const float*)d_in[2];   // [128]
    float* out = (float*)d_out;

    static bool attr_set = false;
    if (!attr_set) {
        cudaFuncSetAttribute(conv_mma_kernel,
                             cudaFuncAttributeMaxDynamicSharedMemorySize, SMEM_TOTAL);
        attr_set = true;
    }

    chsum_kernel<<<B_ * C_, 256>>>(x);
    select_wprep_kernel<<<B_ + (NCHUNK * COUT_ * 64 + 255) / 256, 256>>>(w);
    gather_split_kernel<<<dim3(H_, B_), 256>>>(x);
    conv_mma_kernel<<<dim3(H_ / 2, B_), 256, SMEM_TOTAL>>>(bv, out);
}

// round 6
// speedup vs baseline: 4.2662x; 1.0376x over previous
#include <cuda_runtime.h>
#include <cuda_bf16.h>
#include <cstdint>

// ---------------------------------------------------------------------------
// Problem constants
// ---------------------------------------------------------------------------
#define B_    32
#define C_    128
#define CIN_  64
#define COUT_ 128
#define H_    128
#define W_    128
#define HW_   (H_ * W_)
#define NCHUNK 27            // 18 seg1 (hi,lo)x(hw,hw) + 9 seg2 hi x lw
#define SEG1   18

// ---------------------------------------------------------------------------
// Device scratch (static allocations only)
// ---------------------------------------------------------------------------
__device__ float    g_chsum[B_ * C_];
__device__ int      g_idx[B_ * CIN_];
// Xil[b][y][x][ci] : u32 word = hi(bf16) | lo(bf16)<<16   (134 MB)
__device__ __align__(128) uint32_t g_Xil[(size_t)B_ * H_ * W_ * CIN_];
// Xhi[b][y][x][ciPair] : u32 = hi(2j) | hi(2j+1)<<16       (67 MB)
__device__ __align__(128) uint32_t g_Xhi[(size_t)B_ * H_ * W_ * (CIN_ / 2)];
// Wsplit: 27 chunks x [128 couts x 64 bf16] (linear, k contiguous)
__device__ __align__(128) unsigned short g_Wsplit[NCHUNK * COUT_ * 64];

// ---------------------------------------------------------------------------
// Helpers
// ---------------------------------------------------------------------------
__device__ __forceinline__ uint32_t smem_u32(const void* p) {
    uint32_t a;
    asm("{ .reg .u64 t; cvta.to.shared.u64 t, %1; cvt.u32.u64 %0, t; }" : "=r"(a) : "l"(p));
    return a;
}
__device__ __forceinline__ unsigned short bf16_bits(float v) {
    __nv_bfloat16 h = __float2bfloat16_rn(v);
    return *reinterpret_cast<unsigned short*>(&h);
}
__device__ __forceinline__ float bf16_val(unsigned short u) {
    __nv_bfloat16 h = *reinterpret_cast<__nv_bfloat16*>(&u);
    return __bfloat162float(h);
}

// Swizzled LDS.32 with runtime row stride; 128B swizzle atom within a row block
__device__ __forceinline__ uint32_t ldsw(uint32_t base, int row, int cw, int stride) {
    uint32_t addr = base + (uint32_t)(row * stride) +
                    (uint32_t)(((cw << 2) ^ ((row & 7) << 4)));
    uint32_t v;
    asm volatile("ld.shared.b32 %0, [%1];" : "=r"(v) : "r"(addr));
    return v;
}

__device__ __forceinline__ void mma16816(float* d, uint32_t a0, uint32_t a1,
                                         uint32_t a2, uint32_t a3,
                                         uint32_t b0, uint32_t b1) {
    asm volatile(
        "mma.sync.aligned.m16n8k16.row.col.f32.bf16.bf16.f32 "
        "{%0,%1,%2,%3}, {%4,%5,%6,%7}, {%8,%9}, {%0,%1,%2,%3};"
        : "+f"(d[0]), "+f"(d[1]), "+f"(d[2]), "+f"(d[3])
        : "r"(a0), "r"(a1), "r"(a2), "r"(a3), "r"(b0), "r"(b1));
}

// ---------------------------------------------------------------------------
// Kernel 1: per-channel sums
// ---------------------------------------------------------------------------
__global__ __launch_bounds__(256) void chsum_kernel(const float* __restrict__ x) {
    const int ch = blockIdx.x;
    const float4* p = reinterpret_cast<const float4*>(x) + (size_t)ch * (HW_ / 4);
    float s = 0.f;
    for (int i = threadIdx.x; i < HW_ / 4; i += 256) {
        float4 v = p[i];
        s += (v.x + v.y) + (v.z + v.w);
    }
    #pragma unroll
    for (int o = 16; o; o >>= 1) s += __shfl_down_sync(0xffffffffu, s, o);
    __shared__ float red[8];
    if ((threadIdx.x & 31) == 0) red[threadIdx.x >> 5] = s;
    __syncthreads();
    if (threadIdx.x < 8) {
        s = red[threadIdx.x];
        #pragma unroll
        for (int o = 4; o; o >>= 1) s += __shfl_down_sync(0xffu, s, o);
        if (threadIdx.x == 0) g_chsum[ch] = s;
    }
}

// ---------------------------------------------------------------------------
// Kernel 2: select (blocks 0..31) + weight split/reorder (blocks 32..895)
// ---------------------------------------------------------------------------
__global__ __launch_bounds__(256) void select_wprep_kernel(const float* __restrict__ w) {
    if (blockIdx.x < B_) {
        if (threadIdx.x >= C_) return;
        const int b = blockIdx.x, c = threadIdx.x;
        __shared__ float s[C_];
        s[c] = g_chsum[b * C_ + c];
        __syncthreads();
        const float mine = s[c];
        int rank = 0;
        #pragma unroll 8
        for (int j = 0; j < C_; j++) {
            float v = s[j];
            rank += (v < mine) || (v == mine && j < c);
        }
        if (rank < CIN_) g_idx[b * CIN_ + rank] = c;
    } else {
        int t = (blockIdx.x - B_) * 256 + threadIdx.x;
        if (t >= NCHUNK * COUT_ * 64) return;
        int c = t >> 13;
        int r = (t >> 6) & 127;
        int k = t & 63;
        unsigned short val;
        if (c < SEG1) {
            int tap = c >> 1, ci = (c & 1) * 32 + (k >> 1);
            val = bf16_bits(w[r * (CIN_ * 9) + ci * 9 + tap]);
        } else {
            int tap = c - SEG1, ci = k;
            float wf = w[r * (CIN_ * 9) + ci * 9 + tap];
            unsigned short hu = bf16_bits(wf);
            val = bf16_bits(wf - bf16_val(hu));
        }
        g_Wsplit[t] = val;
    }
}

// ---------------------------------------------------------------------------
// Kernel 3: gather selected channels, CHW->HWC transpose, hi/lo bf16 split
// ---------------------------------------------------------------------------
__global__ __launch_bounds__(256) void gather_split_kernel(const float* __restrict__ x) {
    const int y = blockIdx.x, b = blockIdx.y;
    const int tid = threadIdx.x;
    __shared__ float sv[CIN_][W_ + 1];

    for (int i = tid; i < CIN_ * W_; i += 256) {
        int ci = i >> 7, xx = i & 127;
        int src_c = g_idx[b * CIN_ + ci];
        sv[ci][xx] = x[(((size_t)b * C_ + src_c) * H_ + y) * W_ + xx];
    }
    __syncthreads();

    uint32_t* dst_il = g_Xil + ((size_t)(b * H_ + y)) * W_ * CIN_;
    for (int o = tid; o < W_ * CIN_; o += 256) {
        int xx = o >> 6, ci = o & 63;
        float v = sv[ci][xx];
        unsigned short hu = bf16_bits(v);
        unsigned short lu = bf16_bits(v - bf16_val(hu));
        dst_il[o] = (uint32_t)hu | ((uint32_t)lu << 16);
    }
    uint32_t* dst_hi = g_Xhi + ((size_t)(b * H_ + y)) * W_ * (CIN_ / 2);
    for (int o = tid; o < W_ * (CIN_ / 2); o += 256) {
        int xx = o >> 5, cw = o & 31;
        unsigned short h0 = bf16_bits(sv[2 * cw][xx]);
        unsigned short h1 = bf16_bits(sv[2 * cw + 1][xx]);
        dst_hi[o] = (uint32_t)h0 | ((uint32_t)h1 << 16);
    }
}

// ---------------------------------------------------------------------------
// Kernel 4: conv implicit GEMM, mma.sync bf16, warp tile m32 x n64.
//   CTA = (batch b, 1 output row). M=128 pixels, N=128 couts. 8 warps.
//   2 CTAs / SM (regs capped at 128, SMEM 97KB/CTA) for latency hiding.
//   A staged per (seg, ky): 130 rows with 1-px halo; chunk reads at +kx.
// SMEM (99328B): A0[33280] A1[33280] B0[16384] B1[16384]; epilogue reuses base.
// ---------------------------------------------------------------------------
#define EPI_STRIDE 132            // words; 132 % 32 == 4 -> conflict-free STS
#define A_STAGE_BYTES 33280       // 130 rows x 256B
#define SMEM_TOTAL (2 * A_STAGE_BYTES + 2 * 16384)

extern __shared__ char dynsmem[];

__device__ __forceinline__ int chunk_stage(int t) {
    return (t < SEG1) ? (t / 6) : (3 + (t - SEG1) / 3);
}

__global__ __launch_bounds__(256, 2) void conv_mma_kernel(
    const float* __restrict__ bias, float* __restrict__ out)
{
    const int y = blockIdx.x;                 // 0..127 output row
    const int b = blockIdx.y;                 // 0..31
    const int tid = threadIdx.x;
    const int wid = tid >> 5;
    const int lane = tid & 31;
    const int g = lane >> 2;                  // 0..7
    const int t4 = lane & 3;                  // 0..3
    const int wm = wid & 3;                   // m tile 0..3 (rows of 32)
    const int wn = wid >> 2;                  // n tile 0..1 (cols of 64)

    char* Abuf[2] = { dynsmem, dynsmem + A_STAGE_BYTES };
    char* Bbuf[2] = { dynsmem + 2 * A_STAGE_BYTES, dynsmem + 2 * A_STAGE_BYTES + 16384 };
    float* epi = reinterpret_cast<float*>(dynsmem);

    __shared__ float sbias[COUT_];
    if (tid < COUT_) sbias[tid] = bias[tid];

    float acc[2][8][4];
    #pragma unroll
    for (int mt = 0; mt < 2; mt++)
        #pragma unroll
        for (int nt = 0; nt < 8; nt++)
            #pragma unroll
            for (int r = 0; r < 4; r++) acc[mt][nt][r] = 0.f;

    // ---- A stage prefetch: tile row r -> pixel xx=r-1, input row yy=y+ky-1
    auto prefetchA = [&](int s, int buf) {
        const uint32_t abase = smem_u32(Abuf[buf]);
        if (s < 3) {
            const int yy = y + s - 1;
            const bool rowok = ((unsigned)yy < (unsigned)H_);
            #pragma unroll
            for (int it = 0; it < 9; it++) {
                int i = tid + it * 256;
                if (i < 130 * 16) {
                    int r = i >> 4, j = i & 15;
                    int xx = r - 1;
                    bool valid = rowok && ((unsigned)xx < (unsigned)W_);
                    int yc = valid ? yy : 0, xc = valid ? xx : 0;
                    const char* src = reinterpret_cast<const char*>(
                        g_Xil + (((size_t)(b * H_ + yc) * W_ + xc) * CIN_)) + j * 16;
                    uint32_t dst = abase + (uint32_t)r * 256u + (uint32_t)((j >> 3) * 128) +
                                   (uint32_t)(((j & 7) * 16) ^ ((r & 7) << 4));
                    uint32_t sz = valid ? 16u : 0u;
                    asm volatile("cp.async.cg.shared.global [%0], [%1], 16, %2;"
                                 :: "r"(dst), "l"(src), "r"(sz));
                }
            }
        } else {
            const int yy = y + (s - 3) - 1;
            const bool rowok = ((unsigned)yy < (unsigned)H_);
            #pragma unroll
            for (int it = 0; it < 5; it++) {
                int i = tid + it * 256;
                if (i < 130 * 8) {
                    int r = i >> 3, j = i & 7;
                    int xx = r - 1;
                    bool valid = rowok && ((unsigned)xx < (unsigned)W_);
                    int yc = valid ? yy : 0, xc = valid ? xx : 0;
                    const char* src = reinterpret_cast<const char*>(
                        g_Xhi + (((size_t)(b * H_ + yc) * W_ + xc) * (CIN_ / 2))) + j * 16;
                    uint32_t dst = abase + (uint32_t)r * 128u +
                                   (uint32_t)((j * 16) ^ ((r & 7) << 4));
                    uint32_t sz = valid ? 16u : 0u;
                    asm volatile("cp.async.cg.shared.global [%0], [%1], 16, %2;"
                                 :: "r"(dst), "l"(src), "r"(sz));
                }
            }
        }
    };

    // ---- B chunk prefetch: 16KB
    auto prefetchB = [&](int t, int buf) {
        int c;
        if (t < SEG1) {
            int ky = t / 6, j = t % 6, kx = j % 3, half = j / 3;
            c = (ky * 3 + kx) * 2 + half;
        } else c = t;
        const char* wsrc = reinterpret_cast<const char*>(g_Wsplit) + (size_t)c * 16384;
        const uint32_t bbase = smem_u32(Bbuf[buf]);
        #pragma unroll
        for (int it = 0; it < 4; it++) {
            int i = tid + it * 256;
            int r = i >> 3, j = i & 7;
            uint32_t dst = bbase + (uint32_t)r * 128u +
                           (uint32_t)((j * 16) ^ ((r & 7) << 4));
            asm volatile("cp.async.cg.shared.global [%0], [%1], 16, 16;"
                         :: "r"(dst), "l"(wsrc + (size_t)r * 128 + j * 16));
        }
    };

    // Pre-loop: stage-0 A + chunk-0 B as one group
    prefetchA(0, 0);
    prefetchB(0, 0);
    asm volatile("cp.async.commit_group;" ::: "memory");

    for (int t = 0; t < NCHUNK; t++) {
        const int s = chunk_stage(t);
        const int nxt = t + 1;
        if (nxt < NCHUNK) {
            prefetchB(nxt, nxt & 1);
            int sn = chunk_stage(nxt);
            if (sn != s) prefetchA(sn, sn & 1);
            asm volatile("cp.async.commit_group;" ::: "memory");
            asm volatile("cp.async.wait_group 1;" ::: "memory");
        } else {
            asm volatile("cp.async.wait_group 0;" ::: "memory");
        }
        __syncthreads();

        // chunk params
        int stride, halfoff, kx;
        if (t < SEG1) {
            int j = t % 6;
            kx = j % 3; halfoff = (j / 3) * 128; stride = 256;
        } else {
            kx = (t - SEG1) % 3; halfoff = 0; stride = 128;
        }
        const uint32_t Ab = smem_u32(Abuf[s & 1]) + halfoff;
        const uint32_t Bb = smem_u32(Bbuf[t & 1]);

        #pragma unroll
        for (int ks = 0; ks < 4; ks++) {
            const int c0 = ks * 8;
            uint32_t bf[8][2];
            #pragma unroll
            for (int nt = 0; nt < 8; nt++) {
                int row = wn * 64 + nt * 8 + g;
                bf[nt][0] = ldsw(Bb, row, c0 + t4, 128);
                bf[nt][1] = ldsw(Bb, row, c0 + 4 + t4, 128);
            }
            #pragma unroll
            for (int mt = 0; mt < 2; mt++) {
                int ra = wm * 32 + mt * 16 + g + kx;    // pixel + kx (halo base -1)
                uint32_t a0 = ldsw(Ab, ra,     c0 + t4, stride);
                uint32_t a1 = ldsw(Ab, ra + 8, c0 + t4, stride);
                uint32_t a2 = ldsw(Ab, ra,     c0 + 4 + t4, stride);
                uint32_t a3 = ldsw(Ab, ra + 8, c0 + 4 + t4, stride);
                #pragma unroll
                for (int nt = 0; nt < 8; nt++)
                    mma16816(acc[mt][nt], a0, a1, a2, a3, bf[nt][0], bf[nt][1]);
            }
        }
        __syncthreads();   // protect buffers from next iteration's prefetch
    }

    // ---- epilogue: 2 passes of 64 couts through SMEM, coalesced NCHW stores ----
    #pragma unroll
    for (int p = 0; p < 2; p++) {
        if (wn == p) {
            #pragma unroll
            for (int mt = 0; mt < 2; mt++) {
                int rowm = wm * 32 + mt * 16 + g;
                #pragma unroll
                for (int nt = 0; nt < 8; nt++) {
                    int nl = nt * 8 + 2 * t4;
                    epi[(size_t)nl * EPI_STRIDE + rowm]           = acc[mt][nt][0];
                    epi[(size_t)(nl + 1) * EPI_STRIDE + rowm]     = acc[mt][nt][1];
                    epi[(size_t)nl * EPI_STRIDE + rowm + 8]       = acc[mt][nt][2];
                    epi[(size_t)(nl + 1) * EPI_STRIDE + rowm + 8] = acc[mt][nt][3];
                }
            }
        }
        __syncthreads();
        // 64 couts x 128 pixels = 2048 float4s per pass
        #pragma unroll
        for (int it = 0; it < 8; it++) {
            int i = tid + it * 256;           // 0..2047 float4s
            int nl = i >> 5, mv = i & 31;
            int m = mv * 4;
            float4 v = *reinterpret_cast<float4*>(&epi[(size_t)nl * EPI_STRIDE + m]);
            float bv = sbias[p * 64 + nl];
            v.x += bv; v.y += bv; v.z += bv; v.w += bv;
            *reinterpret_cast<float4*>(
                out + (((size_t)b * COUT_ + p * 64 + nl) * H_ + y) * W_ + m) = v;
        }
        __syncthreads();
    }
}

// ---------------------------------------------------------------------------
extern "C" void kernel_launch(void* const* d_in, const int* in_sizes, int n_in,
                              void* d_out, int out_size) {
    const float* x  = (const float*)d_in[0];   // [32,128,128,128]
    const float* w  = (const float*)d_in[1];   // [128,64,3,3]
    const float* bv = (const float*)d_in[2];   // [128]
    float* out = (float*)d_out;

    static bool attr_set = false;
    if (!attr_set) {
        cudaFuncSetAttribute(conv_mma_kernel,
                             cudaFuncAttributeMaxDynamicSharedMemorySize, SMEM_TOTAL);
        attr_set = true;
    }

    chsum_kernel<<<B_ * C_, 256>>>(x);
    select_wprep_kernel<<<B_ + (NCHUNK * COUT_ * 64 + 255) / 256, 256>>>(w);
    gather_split_kernel<<<dim3(H_, B_), 256>>>(x);
    conv_mma_kernel<<<dim3(H_, B_), 256, SMEM_TOTAL>>>(bv, out);
}

// round 7
// speedup vs baseline: 9.7348x; 2.2818x over previous
#include <cuda_runtime.h>
#include <cuda_bf16.h>
#include <cuda_fp16.h>
#include <cstdint>

// ---------------------------------------------------------------------------
// Problem constants
// ---------------------------------------------------------------------------
#define B_    32
#define C_    128
#define CIN_  64
#define COUT_ 128
#define H_    128
#define W_    128
#define HW_   (H_ * W_)
#define NCHUNK 9             // one K=64 chunk per 3x3 tap, fp16 single-pass

// ---------------------------------------------------------------------------
// Device scratch (static allocations only)
// ---------------------------------------------------------------------------
__device__ float    g_chsum[B_ * C_];
__device__ int      g_idx[B_ * CIN_];
// Xf16[b][y][x][ci] fp16, 64 ci = 128B per pixel (67 MB)
__device__ __align__(128) __half g_Xf16[(size_t)B_ * H_ * W_ * CIN_];
// Wf16: 9 chunks x [128 couts x 64 k] fp16 linear (147 KB)
__device__ __align__(128) __half g_Wf16[NCHUNK * COUT_ * 64];

// ---------------------------------------------------------------------------
// Helpers
// ---------------------------------------------------------------------------
__device__ __forceinline__ uint32_t smem_u32(const void* p) {
    uint32_t a;
    asm("{ .reg .u64 t; cvta.to.shared.u64 t, %1; cvt.u32.u64 %0, t; }" : "=r"(a) : "l"(p));
    return a;
}

// Swizzled LDS.32, fixed 128B row stride; 16B-unit XOR swizzle
__device__ __forceinline__ uint32_t ldsw(uint32_t base, int row, int cw) {
    uint32_t addr = base + (uint32_t)(row << 7) +
                    (uint32_t)(((cw << 2) ^ ((row & 7) << 4)));
    uint32_t v;
    asm volatile("ld.shared.b32 %0, [%1];" : "=r"(v) : "r"(addr));
    return v;
}

__device__ __forceinline__ void mma16816(float* d, uint32_t a0, uint32_t a1,
                                         uint32_t a2, uint32_t a3,
                                         uint32_t b0, uint32_t b1) {
    asm volatile(
        "mma.sync.aligned.m16n8k16.row.col.f32.f16.f16.f32 "
        "{%0,%1,%2,%3}, {%4,%5,%6,%7}, {%8,%9}, {%0,%1,%2,%3};"
        : "+f"(d[0]), "+f"(d[1]), "+f"(d[2]), "+f"(d[3])
        : "r"(a0), "r"(a1), "r"(a2), "r"(a3), "r"(b0), "r"(b1));
}

// ---------------------------------------------------------------------------
// Kernel 1: per-channel sums
// ---------------------------------------------------------------------------
__global__ __launch_bounds__(256) void chsum_kernel(const float* __restrict__ x) {
    const int ch = blockIdx.x;
    const float4* p = reinterpret_cast<const float4*>(x) + (size_t)ch * (HW_ / 4);
    float s = 0.f;
    for (int i = threadIdx.x; i < HW_ / 4; i += 256) {
        float4 v = p[i];
        s += (v.x + v.y) + (v.z + v.w);
    }
    #pragma unroll
    for (int o = 16; o; o >>= 1) s += __shfl_down_sync(0xffffffffu, s, o);
    __shared__ float red[8];
    if ((threadIdx.x & 31) == 0) red[threadIdx.x >> 5] = s;
    __syncthreads();
    if (threadIdx.x < 8) {
        s = red[threadIdx.x];
        #pragma unroll
        for (int o = 4; o; o >>= 1) s += __shfl_down_sync(0xffu, s, o);
        if (threadIdx.x == 0) g_chsum[ch] = s;
    }
}

// ---------------------------------------------------------------------------
// Kernel 2: select (blocks 0..31) + weight fp16 reorder (blocks 32..)
//   chunk t (tap), col k -> w[cout][ci=k][tap]
// ---------------------------------------------------------------------------
__global__ __launch_bounds__(256) void select_wprep_kernel(const float* __restrict__ w) {
    if (blockIdx.x < B_) {
        if (threadIdx.x >= C_) return;
        const int b = blockIdx.x, c = threadIdx.x;
        __shared__ float s[C_];
        s[c] = g_chsum[b * C_ + c];
        __syncthreads();
        const float mine = s[c];
        int rank = 0;
        #pragma unroll 8
        for (int j = 0; j < C_; j++) {
            float v = s[j];
            rank += (v < mine) || (v == mine && j < c);
        }
        if (rank < CIN_) g_idx[b * CIN_ + rank] = c;
    } else {
        int t = (blockIdx.x - B_) * 256 + threadIdx.x;
        if (t >= NCHUNK * COUT_ * 64) return;
        int tap = t >> 13;               // /8192
        int r = (t >> 6) & 127;          // cout
        int k = t & 63;                  // ci
        g_Wf16[t] = __float2half_rn(w[r * (CIN_ * 9) + k * 9 + tap]);
    }
}

// ---------------------------------------------------------------------------
// Kernel 3: gather selected channels, CHW->HWC transpose, fp16 convert
// ---------------------------------------------------------------------------
__global__ __launch_bounds__(256) void gather_split_kernel(const float* __restrict__ x) {
    const int y = blockIdx.x, b = blockIdx.y;
    const int tid = threadIdx.x;
    __shared__ float sv[CIN_][W_ + 1];

    for (int i = tid; i < CIN_ * W_; i += 256) {
        int ci = i >> 7, xx = i & 127;
        int src_c = g_idx[b * CIN_ + ci];
        sv[ci][xx] = x[(((size_t)b * C_ + src_c) * H_ + y) * W_ + xx];
    }
    __syncthreads();

    // Write as u32 words (2 adjacent ci per word), coalesced
    uint32_t* dst = reinterpret_cast<uint32_t*>(
        g_Xf16 + ((size_t)(b * H_ + y)) * W_ * CIN_);
    for (int o = tid; o < W_ * (CIN_ / 2); o += 256) {
        int xx = o >> 5, cw = o & 31;
        __half h0 = __float2half_rn(sv[2 * cw][xx]);
        __half h1 = __float2half_rn(sv[2 * cw + 1][xx]);
        uint32_t w0 = (uint32_t)*reinterpret_cast<unsigned short*>(&h0) |
                      ((uint32_t)*reinterpret_cast<unsigned short*>(&h1) << 16);
        dst[o] = w0;
    }
}

// ---------------------------------------------------------------------------
// Kernel 4: conv implicit GEMM, mma.sync fp16, warp tile m32 x n64.
//   CTA = (batch b, 1 output row). M=128 pixels, N=128 couts. 8 warps.
//   9 chunks (one per tap). A staged per ky (3 stages, 2 bufs); B 3-buf ring.
//   One __syncthreads per chunk (skew-safe: (t+2)%3 != t%3; A stages 3 apart).
// SMEM (82432B): A0[16640] A1[16640] B0..B2[16384]; epilogue reuses base.
// ---------------------------------------------------------------------------
#define EPI_STRIDE 132            // words; 132 % 32 == 4 -> conflict-free STS
#define A_STAGE_BYTES 16640       // 130 rows x 128B
#define SMEM_TOTAL (2 * A_STAGE_BYTES + 3 * 16384)

extern __shared__ char dynsmem[];

__global__ __launch_bounds__(256, 2) void conv_mma_kernel(
    const float* __restrict__ bias, float* __restrict__ out)
{
    const int y = blockIdx.x;                 // 0..127 output row
    const int b = blockIdx.y;                 // 0..31
    const int tid = threadIdx.x;
    const int wid = tid >> 5;
    const int lane = tid & 31;
    const int g = lane >> 2;                  // 0..7
    const int t4 = lane & 3;                  // 0..3
    const int wm = wid & 3;                   // m tile 0..3 (rows of 32)
    const int wn = wid >> 2;                  // n tile 0..1 (cols of 64)

    char* Abuf[2] = { dynsmem, dynsmem + A_STAGE_BYTES };
    char* Bbuf[3] = { dynsmem + 2 * A_STAGE_BYTES,
                      dynsmem + 2 * A_STAGE_BYTES + 16384,
                      dynsmem + 2 * A_STAGE_BYTES + 32768 };
    float* epi = reinterpret_cast<float*>(dynsmem);

    __shared__ float sbias[COUT_];
    if (tid < COUT_) sbias[tid] = bias[tid];

    float acc[2][8][4];
    #pragma unroll
    for (int mt = 0; mt < 2; mt++)
        #pragma unroll
        for (int nt = 0; nt < 8; nt++)
            #pragma unroll
            for (int r = 0; r < 4; r++) acc[mt][nt][r] = 0.f;

    // ---- A stage prefetch: tile row r -> pixel xx=r-1, input row yy=y+ky-1
    auto prefetchA = [&](int s, int buf) {
        const uint32_t abase = smem_u32(Abuf[buf]);
        const int yy = y + s - 1;
        const bool rowok = ((unsigned)yy < (unsigned)H_);
        #pragma unroll
        for (int it = 0; it < 5; it++) {
            int i = tid + it * 256;
            if (i < 130 * 8) {
                int r = i >> 3, j = i & 7;
                int xx = r - 1;
                bool valid = rowok && ((unsigned)xx < (unsigned)W_);
                int yc = valid ? yy : 0, xc = valid ? xx : 0;
                const char* src = reinterpret_cast<const char*>(
                    g_Xf16 + (((size_t)(b * H_ + yc) * W_ + xc) * CIN_)) + j * 16;
                uint32_t dst = abase + (uint32_t)r * 128u +
                               (uint32_t)((j * 16) ^ ((r & 7) << 4));
                uint32_t sz = valid ? 16u : 0u;
                asm volatile("cp.async.cg.shared.global [%0], [%1], 16, %2;"
                             :: "r"(dst), "l"(src), "r"(sz));
            }
        }
    };

    // ---- B chunk prefetch: 16KB
    auto prefetchB = [&](int t, int buf) {
        const char* wsrc = reinterpret_cast<const char*>(g_Wf16) + (size_t)t * 16384;
        const uint32_t bbase = smem_u32(Bbuf[buf]);
        #pragma unroll
        for (int it = 0; it < 4; it++) {
            int i = tid + it * 256;
            int r = i >> 3, j = i & 7;
            uint32_t dst = bbase + (uint32_t)r * 128u +
                           (uint32_t)((j * 16) ^ ((r & 7) << 4));
            asm volatile("cp.async.cg.shared.global [%0], [%1], 16, 16;"
                         :: "r"(dst), "l"(wsrc + (size_t)r * 128 + j * 16));
        }
    };

    // Pre-loop: stage-0 A + chunk-0 B as one group
    prefetchA(0, 0);
    prefetchB(0, 0);
    asm volatile("cp.async.commit_group;" ::: "memory");

    for (int t = 0; t < NCHUNK; t++) {
        const int s = t / 3;                  // ky stage
        const int kx = t - s * 3;
        const int nxt = t + 1;
        if (nxt < NCHUNK) {
            prefetchB(nxt, nxt % 3);
            if (nxt % 3 == 0) prefetchA(nxt / 3, (nxt / 3) & 1);
            asm volatile("cp.async.commit_group;" ::: "memory");
            asm volatile("cp.async.wait_group 1;" ::: "memory");
        } else {
            asm volatile("cp.async.wait_group 0;" ::: "memory");
        }
        __syncthreads();

        const uint32_t Ab = smem_u32(Abuf[s & 1]);
        const uint32_t Bb = smem_u32(Bbuf[t % 3]);

        #pragma unroll
        for (int ks = 0; ks < 4; ks++) {
            const int c0 = ks * 8;
            uint32_t bf[8][2];
            #pragma unroll
            for (int nt = 0; nt < 8; nt++) {
                int row = wn * 64 + nt * 8 + g;
                bf[nt][0] = ldsw(Bb, row, c0 + t4);
                bf[nt][1] = ldsw(Bb, row, c0 + 4 + t4);
            }
            #pragma unroll
            for (int mt = 0; mt < 2; mt++) {
                int ra = wm * 32 + mt * 16 + g + kx;    // pixel + kx (halo base -1)
                uint32_t a0 = ldsw(Ab, ra,     c0 + t4);
                uint32_t a1 = ldsw(Ab, ra + 8, c0 + t4);
                uint32_t a2 = ldsw(Ab, ra,     c0 + 4 + t4);
                uint32_t a3 = ldsw(Ab, ra + 8, c0 + 4 + t4);
                #pragma unroll
                for (int nt = 0; nt < 8; nt++)
                    mma16816(acc[mt][nt], a0, a1, a2, a3, bf[nt][0], bf[nt][1]);
            }
        }
    }

    __syncthreads();   // all compute done before epilogue overwrites SMEM

    // ---- epilogue: 2 passes of 64 couts through SMEM, coalesced NCHW stores ----
    #pragma unroll
    for (int p = 0; p < 2; p++) {
        if (wn == p) {
            #pragma unroll
            for (int mt = 0; mt < 2; mt++) {
                int rowm = wm * 32 + mt * 16 + g;
                #pragma unroll
                for (int nt = 0; nt < 8; nt++) {
                    int nl = nt * 8 + 2 * t4;
                    epi[(size_t)nl * EPI_STRIDE + rowm]           = acc[mt][nt][0];
                    epi[(size_t)(nl + 1) * EPI_STRIDE + rowm]     = acc[mt][nt][1];
                    epi[(size_t)nl * EPI_STRIDE + rowm + 8]       = acc[mt][nt][2];
                    epi[(size_t)(nl + 1) * EPI_STRIDE + rowm + 8] = acc[mt][nt][3];
                }
            }
        }
        __syncthreads();
        // 64 couts x 128 pixels = 2048 float4s per pass
        #pragma unroll
        for (int it = 0; it < 8; it++) {
            int i = tid + it * 256;           // 0..2047 float4s
            int nl = i >> 5, mv = i & 31;
            int m = mv * 4;
            float4 v = *reinterpret_cast<float4*>(&epi[(size_t)nl * EPI_STRIDE + m]);
            float bv = sbias[p * 64 + nl];
            v.x += bv; v.y += bv; v.z += bv; v.w += bv;
            *reinterpret_cast<float4*>(
                out + (((size_t)b * COUT_ + p * 64 + nl) * H_ + y) * W_ + m) = v;
        }
        __syncthreads();
    }
}

// ---------------------------------------------------------------------------
extern "C" void kernel_launch(void* const* d_in, const int* in_sizes, int n_in,
                              void* d_out, int out_size) {
    const float* x  = (const float*)d_in[0];   // [32,128,128,128]
    const float* w  = (const float*)d_in[1];   // [128,64,3,3]
    const float* bv = (const float*)d_in[2];   // [128]
    float* out = (float*)d_out;

    static bool attr_set = false;
    if (!attr_set) {
        cudaFuncSetAttribute(conv_mma_kernel,
                             cudaFuncAttributeMaxDynamicSharedMemorySize, SMEM_TOTAL);
        attr_set = true;
    }

    chsum_kernel<<<B_ * C_, 256>>>(x);
    select_wprep_kernel<<<B_ + (NCHUNK * COUT_ * 64 + 255) / 256, 256>>>(w);
    gather_split_kernel<<<dim3(H_, B_), 256>>>(x);
    conv_mma_kernel<<<dim3(H_, B_), 256, SMEM_TOTAL>>>(bv, out);
}

// round 8
// speedup vs baseline: 10.3277x; 1.0609x over previous
#include <cuda_runtime.h>
#include <cuda_bf16.h>
#include <cuda_fp16.h>
#include <cstdint>

// ---------------------------------------------------------------------------
// Problem constants
// ---------------------------------------------------------------------------
#define B_    32
#define C_    128
#define CIN_  64
#define COUT_ 128
#define H_    128
#define W_    128
#define HW_   (H_ * W_)
#define NCHUNK 9             // one K=64 chunk per 3x3 tap, fp16 single-pass

// ---------------------------------------------------------------------------
// Device scratch (static allocations only)
// ---------------------------------------------------------------------------
__device__ float    g_chsum[B_ * C_];
__device__ int      g_idx[B_ * CIN_];
// Xf16[b][y][x][ci] fp16, 64 ci = 128B per pixel (67 MB)
__device__ __align__(128) __half g_Xf16[(size_t)B_ * H_ * W_ * CIN_];
// Wf16: 9 chunks x [128 couts x 64 k] fp16 linear (147 KB)
__device__ __align__(128) __half g_Wf16[NCHUNK * COUT_ * 64];

// ---------------------------------------------------------------------------
// Helpers
// ---------------------------------------------------------------------------
__device__ __forceinline__ uint32_t smem_u32(const void* p) {
    uint32_t a;
    asm("{ .reg .u64 t; cvta.to.shared.u64 t, %1; cvt.u32.u64 %0, t; }" : "=r"(a) : "l"(p));
    return a;
}

__device__ __forceinline__ void ldsm_x4(uint32_t& r0, uint32_t& r1,
                                        uint32_t& r2, uint32_t& r3, uint32_t addr) {
    asm volatile("ldmatrix.sync.aligned.m8n8.x4.shared.b16 {%0,%1,%2,%3}, [%4];"
                 : "=r"(r0), "=r"(r1), "=r"(r2), "=r"(r3) : "r"(addr));
}

__device__ __forceinline__ void mma16816(float* d, uint32_t a0, uint32_t a1,
                                         uint32_t a2, uint32_t a3,
                                         uint32_t b0, uint32_t b1) {
    asm volatile(
        "mma.sync.aligned.m16n8k16.row.col.f32.f16.f16.f32 "
        "{%0,%1,%2,%3}, {%4,%5,%6,%7}, {%8,%9}, {%0,%1,%2,%3};"
        : "+f"(d[0]), "+f"(d[1]), "+f"(d[2]), "+f"(d[3])
        : "r"(a0), "r"(a1), "r"(a2), "r"(a3), "r"(b0), "r"(b1));
}

// ---------------------------------------------------------------------------
// Kernel 1: per-channel sums
// ---------------------------------------------------------------------------
__global__ __launch_bounds__(256) void chsum_kernel(const float* __restrict__ x) {
    const int ch = blockIdx.x;
    const float4* p = reinterpret_cast<const float4*>(x) + (size_t)ch * (HW_ / 4);
    float s = 0.f;
    for (int i = threadIdx.x; i < HW_ / 4; i += 256) {
        float4 v = p[i];
        s += (v.x + v.y) + (v.z + v.w);
    }
    #pragma unroll
    for (int o = 16; o; o >>= 1) s += __shfl_down_sync(0xffffffffu, s, o);
    __shared__ float red[8];
    if ((threadIdx.x & 31) == 0) red[threadIdx.x >> 5] = s;
    __syncthreads();
    if (threadIdx.x < 8) {
        s = red[threadIdx.x];
        #pragma unroll
        for (int o = 4; o; o >>= 1) s += __shfl_down_sync(0xffu, s, o);
        if (threadIdx.x == 0) g_chsum[ch] = s;
    }
}

// ---------------------------------------------------------------------------
// Kernel 2: select (blocks 0..31) + weight fp16 reorder (blocks 32..)
// ---------------------------------------------------------------------------
__global__ __launch_bounds__(256) void select_wprep_kernel(const float* __restrict__ w) {
    if (blockIdx.x < B_) {
        if (threadIdx.x >= C_) return;
        const int b = blockIdx.x, c = threadIdx.x;
        __shared__ float s[C_];
        s[c] = g_chsum[b * C_ + c];
        __syncthreads();
        const float mine = s[c];
        int rank = 0;
        #pragma unroll 8
        for (int j = 0; j < C_; j++) {
            float v = s[j];
            rank += (v < mine) || (v == mine && j < c);
        }
        if (rank < CIN_) g_idx[b * CIN_ + rank] = c;
    } else {
        int t = (blockIdx.x - B_) * 256 + threadIdx.x;
        if (t >= NCHUNK * COUT_ * 64) return;
        int tap = t >> 13;               // /8192
        int r = (t >> 6) & 127;          // cout
        int k = t & 63;                  // ci
        g_Wf16[t] = __float2half_rn(w[r * (CIN_ * 9) + k * 9 + tap]);
    }
}

// ---------------------------------------------------------------------------
// Kernel 3: gather selected channels, CHW->HWC transpose, fp16 convert
// ---------------------------------------------------------------------------
__global__ __launch_bounds__(256) void gather_split_kernel(const float* __restrict__ x) {
    const int y = blockIdx.x, b = blockIdx.y;
    const int tid = threadIdx.x;
    __shared__ float sv[CIN_][W_ + 1];

    for (int i = tid; i < CIN_ * W_; i += 256) {
        int ci = i >> 7, xx = i & 127;
        int src_c = g_idx[b * CIN_ + ci];
        sv[ci][xx] = x[(((size_t)b * C_ + src_c) * H_ + y) * W_ + xx];
    }
    __syncthreads();

    uint32_t* dst = reinterpret_cast<uint32_t*>(
        g_Xf16 + ((size_t)(b * H_ + y)) * W_ * CIN_);
    for (int o = tid; o < W_ * (CIN_ / 2); o += 256) {
        int xx = o >> 5, cw = o & 31;
        __half h0 = __float2half_rn(sv[2 * cw][xx]);
        __half h1 = __float2half_rn(sv[2 * cw + 1][xx]);
        uint32_t w0 = (uint32_t)*reinterpret_cast<unsigned short*>(&h0) |
                      ((uint32_t)*reinterpret_cast<unsigned short*>(&h1) << 16);
        dst[o] = w0;
    }
}

// ---------------------------------------------------------------------------
// Kernel 4: conv implicit GEMM, mma.sync fp16, ldmatrix fragment loads.
//   CTA = (batch b, 1 output row). M=128 pixels, N=128 couts. 8 warps m32n64.
//   9 chunks (one per tap). A staged per ky (3 stages, 2 bufs); B 3-buf ring.
// SMEM (82432B): A0[16640] A1[16640] B0..B2[16384]; epilogue reuses base.
// ---------------------------------------------------------------------------
#define EPI_STRIDE 132            // words; 132 % 32 == 4 -> conflict-free STS
#define A_STAGE_BYTES 16640       // 130 rows x 128B
#define SMEM_TOTAL (2 * A_STAGE_BYTES + 3 * 16384)

extern __shared__ char dynsmem[];

__global__ __launch_bounds__(256, 2) void conv_mma_kernel(
    const float* __restrict__ bias, float* __restrict__ out)
{
    const int y = blockIdx.x;                 // 0..127 output row
    const int b = blockIdx.y;                 // 0..31
    const int tid = threadIdx.x;
    const int wid = tid >> 5;
    const int lane = tid & 31;
    const int g = lane >> 2;                  // 0..7
    const int t4 = lane & 3;                  // 0..3
    const int wm = wid & 3;                   // m tile 0..3 (rows of 32)
    const int wn = wid >> 2;                  // n tile 0..1 (cols of 64)

    char* Abuf[2] = { dynsmem, dynsmem + A_STAGE_BYTES };
    char* Bbuf[3] = { dynsmem + 2 * A_STAGE_BYTES,
                      dynsmem + 2 * A_STAGE_BYTES + 16384,
                      dynsmem + 2 * A_STAGE_BYTES + 32768 };
    float* epi = reinterpret_cast<float*>(dynsmem);

    __shared__ float sbias[COUT_];
    if (tid < COUT_) sbias[tid] = bias[tid];

    // ldmatrix lane geometry
    const int laneA = lane & 15;              // row-in-16 for A matrices
    const int unitA_half = lane >> 4;         // +0/+1 16B unit
    const int laneB = (lane & 7) + ((lane >> 4) << 3);  // row-in-16 for B
    const int unitB_half = (lane >> 3) & 1;

    float acc[2][8][4];
    #pragma unroll
    for (int mt = 0; mt < 2; mt++)
        #pragma unroll
        for (int nt = 0; nt < 8; nt++)
            #pragma unroll
            for (int r = 0; r < 4; r++) acc[mt][nt][r] = 0.f;

    // ---- A stage prefetch: tile row r -> pixel xx=r-1, input row yy=y+ky-1
    auto prefetchA = [&](int s, int buf) {
        const uint32_t abase = smem_u32(Abuf[buf]);
        const int yy = y + s - 1;
        const bool rowok = ((unsigned)yy < (unsigned)H_);
        #pragma unroll
        for (int it = 0; it < 5; it++) {
            int i = tid + it * 256;
            if (i < 130 * 8) {
                int r = i >> 3, j = i & 7;
                int xx = r - 1;
                bool valid = rowok && ((unsigned)xx < (unsigned)W_);
                int yc = valid ? yy : 0, xc = valid ? xx : 0;
                const char* src = reinterpret_cast<const char*>(
                    g_Xf16 + (((size_t)(b * H_ + yc) * W_ + xc) * CIN_)) + j * 16;
                uint32_t dst = abase + (uint32_t)r * 128u +
                               (uint32_t)((j * 16) ^ ((r & 7) << 4));
                uint32_t sz = valid ? 16u : 0u;
                asm volatile("cp.async.cg.shared.global [%0], [%1], 16, %2;"
                             :: "r"(dst), "l"(src), "r"(sz));
            }
        }
    };

    // ---- B chunk prefetch: 16KB
    auto prefetchB = [&](int t, int buf) {
        const char* wsrc = reinterpret_cast<const char*>(g_Wf16) + (size_t)t * 16384;
        const uint32_t bbase = smem_u32(Bbuf[buf]);
        #pragma unroll
        for (int it = 0; it < 4; it++) {
            int i = tid + it * 256;
            int r = i >> 3, j = i & 7;
            uint32_t dst = bbase + (uint32_t)r * 128u +
                           (uint32_t)((j * 16) ^ ((r & 7) << 4));
            asm volatile("cp.async.cg.shared.global [%0], [%1], 16, 16;"
                         :: "r"(dst), "l"(wsrc + (size_t)r * 128 + j * 16));
        }
    };

    // Pre-loop: stage-0 A + chunk-0 B as one group
    prefetchA(0, 0);
    prefetchB(0, 0);
    asm volatile("cp.async.commit_group;" ::: "memory");

    for (int t = 0; t < NCHUNK; t++) {
        const int s = t / 3;                  // ky stage
        const int kx = t - s * 3;
        const int nxt = t + 1;
        if (nxt < NCHUNK) {
            prefetchB(nxt, nxt % 3);
            if (nxt % 3 == 0) prefetchA(nxt / 3, (nxt / 3) & 1);
            asm volatile("cp.async.commit_group;" ::: "memory");
            asm volatile("cp.async.wait_group 1;" ::: "memory");
        } else {
            asm volatile("cp.async.wait_group 0;" ::: "memory");
        }
        __syncthreads();

        const uint32_t Ab = smem_u32(Abuf[s & 1]);
        const uint32_t Bb = smem_u32(Bbuf[t % 3]);

        // Per-thread fixed row components
        const int rowB0 = wn * 64 + laneB;                 // + nt2*16
        const int rowA0 = wm * 32 + laneA + kx;            // + mt*16

        #pragma unroll
        for (int ks = 0; ks < 4; ks++) {
            uint32_t bf[8][2];
            #pragma unroll
            for (int nt2 = 0; nt2 < 4; nt2++) {
                int row = rowB0 + nt2 * 16;
                uint32_t addr = Bb + (uint32_t)(row << 7) +
                    (uint32_t)((((ks * 2 + unitB_half) << 4)) ^ ((row & 7) << 4));
                ldsm_x4(bf[2 * nt2][0], bf[2 * nt2][1],
                        bf[2 * nt2 + 1][0], bf[2 * nt2 + 1][1], addr);
            }
            #pragma unroll
            for (int mt = 0; mt < 2; mt++) {
                int row = rowA0 + mt * 16;
                uint32_t addr = Ab + (uint32_t)(row << 7) +
                    (uint32_t)((((ks * 2 + unitA_half) << 4)) ^ ((row & 7) << 4));
                uint32_t a0, a1, a2, a3;
                ldsm_x4(a0, a1, a2, a3, addr);
                #pragma unroll
                for (int nt = 0; nt < 8; nt++)
                    mma16816(acc[mt][nt], a0, a1, a2, a3, bf[nt][0], bf[nt][1]);
            }
        }
    }

    __syncthreads();   // all compute done before epilogue overwrites SMEM

    // ---- epilogue: 2 passes of 64 couts through SMEM, coalesced NCHW stores ----
    #pragma unroll
    for (int p = 0; p < 2; p++) {
        if (wn == p) {
            #pragma unroll
            for (int mt = 0; mt < 2; mt++) {
                int rowm = wm * 32 + mt * 16 + g;
                #pragma unroll
                for (int nt = 0; nt < 8; nt++) {
                    int nl = nt * 8 + 2 * t4;
                    epi[(size_t)nl * EPI_STRIDE + rowm]           = acc[mt][nt][0];
                    epi[(size_t)(nl + 1) * EPI_STRIDE + rowm]     = acc[mt][nt][1];
                    epi[(size_t)nl * EPI_STRIDE + rowm + 8]       = acc[mt][nt][2];
                    epi[(size_t)(nl + 1) * EPI_STRIDE + rowm + 8] = acc[mt][nt][3];
                }
            }
        }
        __syncthreads();
        // 64 couts x 128 pixels = 2048 float4s per pass
        #pragma unroll
        for (int it = 0; it < 8; it++) {
            int i = tid + it * 256;           // 0..2047 float4s
            int nl = i >> 5, mv = i & 31;
            int m = mv * 4;
            float4 v = *reinterpret_cast<float4*>(&epi[(size_t)nl * EPI_STRIDE + m]);
            float bv = sbias[p * 64 + nl];
            v.x += bv; v.y += bv; v.z += bv; v.w += bv;
            *reinterpret_cast<float4*>(
                out + (((size_t)b * COUT_ + p * 64 + nl) * H_ + y) * W_ + m) = v;
        }
        __syncthreads();
    }
}

// ---------------------------------------------------------------------------
extern "C" void kernel_launch(void* const* d_in, const int* in_sizes, int n_in,
                              void* d_out, int out_size) {
    const float* x  = (const float*)d_in[0];   // [32,128,128,128]
    const float* w  = (const float*)d_in[1];   // [128,64,3,3]
    const float* bv = (const float*)d_in[2];   // [128]
    float* out = (float*)d_out;

    static bool attr_set = false;
    if (!attr_set) {
        cudaFuncSetAttribute(conv_mma_kernel,
                             cudaFuncAttributeMaxDynamicSharedMemorySize, SMEM_TOTAL);
        attr_set = true;
    }

    chsum_kernel<<<B_ * C_, 256>>>(x);
    select_wprep_kernel<<<B_ + (NCHUNK * COUT_ * 64 + 255) / 256, 256>>>(w);
    gather_split_kernel<<<dim3(H_, B_), 256>>>(x);
    conv_mma_kernel<<<dim3(H_, B_), 256, SMEM_TOTAL>>>(bv, out);
}